// round 17
// baseline (speedup 1.0000x reference)
#include <cuda_runtime.h>
#include <cuda_bf16.h>
#include <stdint.h>

// NearestMean: out[i] = labels[ sum_j (x[i] >= thresholds[j]) ], float32 output.
// Landscape: all ILP=4 shapes sit at kernel 159-162us / DRAM 85-86.5% (HBM floor).
// R16 probe: ILP=8 (half the threads, MLP=8 per thread) to test whether deeper
// per-warp outstanding loads lift DRAM% past 86. If neutral -> floor confirmed.

// ---------- param decode (uniform, negligible cost) ----------
__device__ __forceinline__ float decode_label_word(uint32_t w) {
    if (w == 0u) return 0.0f;
    float f = __uint_as_float(w);
    float af = fabsf(f);
    uint32_t exp = (w >> 23) & 0xFFu;
    if (exp != 0xFFu && af >= 1e-6f && af <= 1e6f) return f;   // plausible float32
    return (float)(int)w;                                       // else int32 bits
}

__device__ __forceinline__ void decode_params(
    const void* __restrict__ thrRaw, const void* __restrict__ labsRaw,
    float& t0, float& t1, float& t2,
    float& l0, float& l1, float& l2, float& l3)
{
    const float* pf = (const float*)thrRaw;
    float a = pf[0], b = pf[1], c = pf[2];
    bool ok = isfinite(a) && isfinite(b) && isfinite(c) &&
              (a < b) && (b < c) && fabsf(a) < 1e8f && fabsf(c) < 1e8f;
    if (!ok) {
        const double* pd = (const double*)thrRaw;
        a = (float)pd[0]; b = (float)pd[1]; c = (float)pd[2];
    }
    t0 = a; t1 = b; t2 = c;

    const uint32_t* lr = (const uint32_t*)labsRaw;
    uint32_t w0 = lr[0], w1 = lr[1], w2 = lr[2], w3 = lr[3];
    if (w1 == 0u && w3 == 0u && (w2 != 0u || w0 != 0u)) {      // int64 signature
        l0 = (float)(int)lr[0];
        l1 = (float)(int)lr[2];
        l2 = (float)(int)lr[4];
        l3 = (float)(int)lr[6];
    } else {
        l0 = decode_label_word(w0);
        l1 = decode_label_word(w1);
        l2 = decode_label_word(w2);
        l3 = decode_label_word(w3);
    }
}

// ---------- hot path ----------
__device__ __forceinline__ float bucket(float v, float t0, float t1, float t2,
                                        float l0, float l1, float l2, float l3)
{
    float r = (v >= t2) ? l3 : l2;
    r = (v >= t1) ? r : l1;
    r = (v >= t0) ? r : l0;
    return r;
}

__device__ __forceinline__ float4 bucket4(float4 v, float t0, float t1, float t2,
                                          float l0, float l1, float l2, float l3)
{
    float4 r;
    r.x = bucket(v.x, t0, t1, t2, l0, l1, l2, l3);
    r.y = bucket(v.y, t0, t1, t2, l0, l1, l2, l3);
    r.z = bucket(v.z, t0, t1, t2, l0, l1, l2, l3);
    r.w = bucket(v.w, t0, t1, t2, l0, l1, l2, l3);
    return r;
}

#define NM_ILP 8

// ILP=8, 32-bit indexing, R8-style predicated front-batched loads.
__global__ __launch_bounds__(256) void nm_vec4_ilp8(
    const float4* __restrict__ x4,
    const void* __restrict__ thrRaw,
    const void* __restrict__ labsRaw,
    float4* __restrict__ out4,
    unsigned n4)
{
    float t0, t1, t2, l0, l1, l2, l3;
    decode_params(thrRaw, labsRaw, t0, t1, t2, l0, l1, l2, l3);

    unsigned base = blockIdx.x * (256u * NM_ILP) + threadIdx.x;

    float4 v[NM_ILP];
    bool ok[NM_ILP];
    #pragma unroll
    for (int k = 0; k < NM_ILP; k++) {
        unsigned i = base + (unsigned)k * 256u;
        ok[k] = (i < n4);
        if (ok[k]) v[k] = x4[i];      // front-batched LDG.128s -> MLP up to 8
    }

    #pragma unroll
    for (int k = 0; k < NM_ILP; k++) {
        if (ok[k]) {
            unsigned i = base + (unsigned)k * 256u;
            out4[i] = bucket4(v[k], t0, t1, t2, l0, l1, l2, l3);
        }
    }
}

// 64-bit index fallback (enormous n), ILP=4 known-good shape.
__global__ __launch_bounds__(256) void nm_vec4_ll(
    const float4* __restrict__ x4,
    const void* __restrict__ thrRaw,
    const void* __restrict__ labsRaw,
    float4* __restrict__ out4,
    long long n4)
{
    float t0, t1, t2, l0, l1, l2, l3;
    decode_params(thrRaw, labsRaw, t0, t1, t2, l0, l1, l2, l3);

    long long base = (long long)blockIdx.x * (256 * 4) + threadIdx.x;

    #pragma unroll
    for (int k = 0; k < 4; k++) {
        long long i = base + (long long)k * 256;
        if (i < n4)
            out4[i] = bucket4(x4[i], t0, t1, t2, l0, l1, l2, l3);
    }
}

__global__ __launch_bounds__(256) void nm_scalar(
    const float* __restrict__ x,
    const void* __restrict__ thrRaw,
    const void* __restrict__ labsRaw,
    float* __restrict__ out,
    long long n)
{
    float t0, t1, t2, l0, l1, l2, l3;
    decode_params(thrRaw, labsRaw, t0, t1, t2, l0, l1, l2, l3);

    long long i = (long long)blockIdx.x * blockDim.x + threadIdx.x;
    if (i >= n) return;
    out[i] = bucket(x[i], t0, t1, t2, l0, l1, l2, l3);
}

extern "C" void kernel_launch(void* const* d_in, const int* in_sizes, int n_in,
                              void* d_out, int out_size)
{
    // Identify inputs by element count: X = largest; thresholds = smaller small
    // array (K-1); labels = larger small array (K).
    int xi = 0;
    for (int k = 1; k < n_in; k++)
        if (in_sizes[k] > in_sizes[xi]) xi = k;

    int ti = -1, li = -1;
    for (int k = 0; k < n_in; k++) {
        if (k == xi) continue;
        if (ti < 0) { ti = k; continue; }
        li = k;
    }
    if (ti >= 0 && li >= 0 && in_sizes[ti] > in_sizes[li]) {
        int tmp = ti; ti = li; li = tmp;
    }
    if (li < 0) li = ti;

    const float* X = (const float*)d_in[xi];
    float* out = (float*)d_out;
    long long n = (long long)in_sizes[xi];

    bool aligned = (((uintptr_t)X & 15u) == 0) && (((uintptr_t)out & 15u) == 0);

    if (aligned && (n % 4 == 0)) {
        long long n4 = n / 4;
        if (n4 <= 0x7FFFFFFFLL) {
            const long long tile = 256LL * NM_ILP;
            long long blocks = (n4 + tile - 1) / tile;
            nm_vec4_ilp8<<<(unsigned)blocks, 256>>>(
                (const float4*)X, d_in[ti], d_in[li], (float4*)out, (unsigned)n4);
        } else {
            const long long tile = 256LL * 4;
            long long blocks = (n4 + tile - 1) / tile;
            nm_vec4_ll<<<(unsigned)blocks, 256>>>(
                (const float4*)X, d_in[ti], d_in[li], (float4*)out, n4);
        }
    } else {
        long long blocks = (n + 255) / 256;
        nm_scalar<<<(unsigned)blocks, 256>>>(X, d_in[ti], d_in[li], out, n);
    }
}